// round 11
// baseline (speedup 1.0000x reference)
#include <cuda_runtime.h>
#include <cuda_bf16.h>

#define N_NODES 50000
#define N_EDGES 1600000
#define OUT_H   (N_NODES * 96)        // 4,800,000
#define OUT_MU  OUT_H                 // mean_up offset
#define OUT_MD  (OUT_H + N_EDGES)     // mean_down offset

// ---------------- scratch (device globals; no allocation allowed) ----------------
__device__ int   g_is64;
__device__ __align__(16) int   g_row[N_EDGES];
__device__ __align__(16) int   g_col[N_EDGES];
__device__ float g_cnt_row[N_NODES];
__device__ float g_cnt_col[N_NODES];
__device__ float g_dinv_row[N_NODES];
__device__ float g_dinv_col[N_NODES];
__device__ __align__(16) float g_tmp_up[N_NODES * 32];
__device__ __align__(16) float g_tmp_down[N_NODES * 32];
__device__ __align__(16) float g_bufA[N_NODES * 96];
__device__ __align__(16) float g_bufB[N_NODES * 96];

// ---------------- 0. detect int64 vs int32 edge_index ----------------
// int64 little-endian with values < 50000 -> every odd 32-bit word is 0.
// int32 -> odd words are random node ids, OR over 2048 of them != 0 (p ~ 0).
__global__ void k_detect(const int* __restrict__ ei)
{
    __shared__ int sh[256];
    int acc = 0;
    for (int k = threadIdx.x; k < 2048; k += 256)
        acc |= ei[2 * k + 1];
    sh[threadIdx.x] = acc;
    __syncthreads();
    for (int s = 128; s; s >>= 1) {
        if (threadIdx.x < s) sh[threadIdx.x] |= sh[threadIdx.x + s];
        __syncthreads();
    }
    if (threadIdx.x == 0) g_is64 = (sh[0] == 0) ? 1 : 0;
}

// ---------------- 1. zero degree counters ----------------
__global__ void k_zero()
{
    int i = blockIdx.x * blockDim.x + threadIdx.x;
    if (i < N_NODES) { g_cnt_row[i] = 0.f; g_cnt_col[i] = 0.f; }
}

// ---------------- 2. convert edge index + count degrees ----------------
__global__ void k_prep(const int* __restrict__ ei)
{
    int e = blockIdx.x * blockDim.x + threadIdx.x;
    if (e >= N_EDGES) return;
    int is64 = g_is64;
    int r, c;
    if (is64) {
        r = ei[2 * e];
        c = ei[2 * (N_EDGES + e)];
    } else {
        r = ei[e];
        c = ei[N_EDGES + e];
    }
    g_row[e] = r;
    g_col[e] = c;
    atomicAdd(&g_cnt_row[r], 1.0f);
    atomicAdd(&g_cnt_col[c], 1.0f);
}

// ---------------- 3. invert degrees ----------------
__global__ void k_inv()
{
    int i = blockIdx.x * blockDim.x + threadIdx.x;
    if (i >= N_NODES) return;
    float cr = g_cnt_row[i], cc = g_cnt_col[i];
    g_dinv_row[i] = cr > 0.f ? 1.0f / cr : 0.0f;
    g_dinv_col[i] = cc > 0.f ? 1.0f / cc : 0.0f;
}

// ---------------- 4. edge-weight means ----------------
__global__ void k_mean(const float* __restrict__ u1, const float* __restrict__ u2,
                       const float* __restrict__ u3, const float* __restrict__ d1,
                       const float* __restrict__ d2, const float* __restrict__ d3,
                       float* __restrict__ out)
{
    int e = blockIdx.x * blockDim.x + threadIdx.x;
    if (e >= N_EDGES) return;
    out[OUT_MU + e] = (u1[e] + u2[e] + u3[e]) / 3.0f;
    out[OUT_MD + e] = (d1[e] + d2[e] + d3[e]) / 3.0f;
}

// ---------------- 5. fused 3-matrix GEMM per layer ----------------
// block = 128 threads = 4 nodes x 32 output cols. Each thread computes the
// up/down/bias projections for one (node, j) pair, writes tmp_up/tmp_down,
// writes bias directly into cat[:,64:96], and zeroes cat[:,0:64].
template <int DIN>
__global__ void k_gemm(const float* __restrict__ hparam, int hsel,
                       const float* __restrict__ wu, const float* __restrict__ wd,
                       const float* __restrict__ wb, int bufsel)
{
    __shared__ float Wsh[DIN * 96];   // Wsh[k*96 + m]: m<32 up, <64 down, else bias
    __shared__ float hsh[4 * DIN];
    const float* h = (hsel == 0) ? hparam : (hsel == 1 ? g_bufA : g_bufB);
    float* cat = bufsel ? g_bufB : g_bufA;

    int tid = threadIdx.x;
    for (int idx = tid; idx < DIN * 96; idx += 128) {
        int k = idx / 96, m = idx % 96;
        float v;
        if (m < 32)      v = wu[m * DIN + k];
        else if (m < 64) v = wd[(m - 32) * DIN + k];
        else             v = wb[(m - 64) * DIN + k];
        Wsh[idx] = v;
    }
    int n0 = blockIdx.x * 4;
    for (int idx = tid; idx < 4 * DIN; idx += 128)
        hsh[idx] = h[n0 * DIN + idx];
    __syncthreads();

    int i = tid >> 5;       // node within block
    int j = tid & 31;       // output column
    float au = 0.f, ad = 0.f, ab = 0.f;
#pragma unroll
    for (int k = 0; k < DIN; k++) {
        float hv = hsh[i * DIN + k];
        au = fmaf(hv, Wsh[k * 96 + j], au);
        ad = fmaf(hv, Wsh[k * 96 + 32 + j], ad);
        ab = fmaf(hv, Wsh[k * 96 + 64 + j], ab);
    }
    int n = n0 + i;
    g_tmp_up[n * 32 + j]   = au;
    g_tmp_down[n * 32 + j] = ad;
    cat[n * 96 + j]        = 0.f;
    cat[n * 96 + 32 + j]   = 0.f;
    cat[n * 96 + 64 + j]   = ab;
}

// ---------------- 6. edge propagate (scatter-add with vector RED) ----------------
// 8 threads per edge, each handles one float4 of the 32-wide feature row.
__global__ void k_edge(int dir /*0=up,1=down*/, const float* __restrict__ ew, int bufsel)
{
    int tid = blockIdx.x * blockDim.x + threadIdx.x;   // < E*8 = 12.8M
    int e = tid >> 3;
    int q = tid & 7;
    if (e >= N_EDGES) return;

    const int*   src  = dir ? g_col      : g_row;
    const int*   dst  = dir ? g_row      : g_col;
    const float* dinv = dir ? g_dinv_row : g_dinv_col;
    const float* tmp  = dir ? g_tmp_down : g_tmp_up;
    float* cat = (bufsel ? g_bufB : g_bufA) + dir * 32;

    int s = __ldg(&src[e]);
    int d = __ldg(&dst[e]);
    float w = __ldg(&dinv[d]) * __ldg(&ew[e]);

    const float4 v = *reinterpret_cast<const float4*>(tmp + s * 32 + q * 4);
    float* p = cat + (size_t)d * 96 + q * 4;   // 16B-aligned by construction
    asm volatile("red.global.add.v4.f32 [%0], {%1, %2, %3, %4};"
                 :: "l"(p), "f"(v.x * w), "f"(v.y * w), "f"(v.z * w), "f"(v.w * w)
                 : "memory");
}

// ---------------- 7. L2-normalize rows + leaky relu ----------------
// One warp per node; lane handles cols {lane, lane+32, lane+64}.
__global__ void k_norm(int bufsel, float* __restrict__ out, int toOut)
{
    int gt = blockIdx.x * blockDim.x + threadIdx.x;
    int n = gt >> 5;
    int lane = gt & 31;
    if (n >= N_NODES) return;
    const float* cat = bufsel ? g_bufB : g_bufA;
    float a = cat[n * 96 + lane];
    float b = cat[n * 96 + 32 + lane];
    float c = cat[n * 96 + 64 + lane];
    float ss = a * a + b * b + c * c;
#pragma unroll
    for (int o = 16; o; o >>= 1) ss += __shfl_xor_sync(0xFFFFFFFFu, ss, o);
    float inv = 1.0f / fmaxf(sqrtf(ss), 1e-12f);
    float* dstp = toOut ? out : (bufsel ? g_bufB : g_bufA);
    float va = a * inv; va = va >= 0.f ? va : 0.1f * va;
    float vb = b * inv; vb = vb >= 0.f ? vb : 0.1f * vb;
    float vc = c * inv; vc = vc >= 0.f ? vc : 0.1f * vc;
    dstp[n * 96 + lane]      = va;
    dstp[n * 96 + 32 + lane] = vb;
    dstp[n * 96 + 64 + lane] = vc;
}

// ---------------- host launch ----------------
extern "C" void kernel_launch(void* const* d_in, const int* in_sizes, int n_in,
                              void* d_out, int out_size)
{
    const float* x   = (const float*)d_in[0];
    const int*   ei  = (const int*)d_in[1];     // int32 or int64 words; auto-detected
    const float* w1u = (const float*)d_in[2];
    const float* w1d = (const float*)d_in[3];
    const float* w1b = (const float*)d_in[4];
    const float* e1u = (const float*)d_in[5];
    const float* e1d = (const float*)d_in[6];
    const float* w2u = (const float*)d_in[7];
    const float* w2d = (const float*)d_in[8];
    const float* w2b = (const float*)d_in[9];
    const float* e2u = (const float*)d_in[10];
    const float* e2d = (const float*)d_in[11];
    const float* w3u = (const float*)d_in[12];
    const float* w3d = (const float*)d_in[13];
    const float* w3b = (const float*)d_in[14];
    const float* e3u = (const float*)d_in[15];
    const float* e3d = (const float*)d_in[16];
    float* out = (float*)d_out;

    const int NB_N    = (N_NODES + 255) / 256;       // 196
    const int NB_E    = N_EDGES / 256;               // 6250
    const int NB_E8   = (N_EDGES * 8) / 256;         // 50000
    const int NB_GEMM = N_NODES / 4;                 // 12500
    const int NB_NORM = (N_NODES * 32 + 255) / 256;  // 6250

    // ---- prep ----
    k_detect<<<1, 256>>>(ei);
    k_zero<<<NB_N, 256>>>();
    k_prep<<<NB_E, 256>>>(ei);
    k_inv<<<NB_N, 256>>>();
    k_mean<<<NB_E, 256>>>(e1u, e2u, e3u, e1d, e2d, e3d, out);

    // ---- layer 1: x (N x 8) -> bufA ----
    k_gemm<8><<<NB_GEMM, 128>>>(x, 0, w1u, w1d, w1b, 0);
    k_edge<<<NB_E8, 256>>>(0, e1u, 0);
    k_edge<<<NB_E8, 256>>>(1, e1d, 0);
    k_norm<<<NB_NORM, 256>>>(0, nullptr, 0);

    // ---- layer 2: bufA (N x 96) -> bufB ----
    k_gemm<96><<<NB_GEMM, 128>>>(nullptr, 1, w2u, w2d, w2b, 1);
    k_edge<<<NB_E8, 256>>>(0, e2u, 1);
    k_edge<<<NB_E8, 256>>>(1, e2d, 1);
    k_norm<<<NB_NORM, 256>>>(1, nullptr, 0);

    // ---- layer 3: bufB (N x 96) -> bufA -> out ----
    k_gemm<96><<<NB_GEMM, 128>>>(nullptr, 2, w3u, w3d, w3b, 0);
    k_edge<<<NB_E8, 256>>>(0, e3u, 0);
    k_edge<<<NB_E8, 256>>>(1, e3d, 0);
    k_norm<<<NB_NORM, 256>>>(0, out, 1);
}

// round 12
// speedup vs baseline: 2.1884x; 2.1884x over previous
#include <cuda_runtime.h>
#include <cuda_bf16.h>

#define N_NODES 50000
#define N_EDGES 1600000
#define OUT_H   (N_NODES * 96)
#define OUT_MU  OUT_H
#define OUT_MD  (OUT_H + N_EDGES)

// ---------------- scratch (device globals; no allocation allowed) ----------------
__device__ int   g_is64;
__device__ __align__(16) int   g_row[N_EDGES];
__device__ __align__(16) int   g_col[N_EDGES];
__device__ int   g_cnt_up[N_NODES];        // degree by col (up direction dst)
__device__ int   g_cnt_dn[N_NODES];        // degree by row (down direction dst)
__device__ int   g_off_up[N_NODES + 1];
__device__ int   g_off_dn[N_NODES + 1];
__device__ int   g_cur_up[N_NODES];
__device__ int   g_cur_dn[N_NODES];
__device__ __align__(16) int2  g_csr_up[N_EDGES];   // (src=row, eid), bucketed by col
__device__ __align__(16) int2  g_csr_dn[N_EDGES];   // (src=col, eid), bucketed by row
__device__ __align__(16) float g_tmp_up[N_NODES * 32];
__device__ __align__(16) float g_tmp_down[N_NODES * 32];
__device__ __align__(16) float g_bias[N_NODES * 32];
__device__ __align__(16) float g_h[N_NODES * 96];

// ---------------- 0. detect int64 vs int32 edge_index ----------------
__global__ void k_detect(const int* __restrict__ ei)
{
    __shared__ int sh[256];
    int acc = 0;
    for (int k = threadIdx.x; k < 2048; k += 256)
        acc |= ei[2 * k + 1];
    sh[threadIdx.x] = acc;
    __syncthreads();
    for (int s = 128; s; s >>= 1) {
        if (threadIdx.x < s) sh[threadIdx.x] |= sh[threadIdx.x + s];
        __syncthreads();
    }
    if (threadIdx.x == 0) g_is64 = (sh[0] == 0) ? 1 : 0;
}

// ---------------- 1. zero degree counters ----------------
__global__ void k_zero()
{
    int i = blockIdx.x * blockDim.x + threadIdx.x;
    if (i < N_NODES) { g_cnt_up[i] = 0; g_cnt_dn[i] = 0; }
}

// ---------------- 2. convert edge index + count degrees ----------------
__global__ void k_prep(const int* __restrict__ ei)
{
    int e = blockIdx.x * blockDim.x + threadIdx.x;
    if (e >= N_EDGES) return;
    int is64 = g_is64;
    int r, c;
    if (is64) {
        r = ei[2 * e];
        c = ei[2 * (N_EDGES + e)];
    } else {
        r = ei[e];
        c = ei[N_EDGES + e];
    }
    g_row[e] = r;
    g_col[e] = c;
    atomicAdd(&g_cnt_up[c], 1);   // up: dst = col
    atomicAdd(&g_cnt_dn[r], 1);   // down: dst = row
}

// ---------------- 3. exclusive scan (single block, both arrays) ----------------
__device__ void scan_one(const int* __restrict__ cnt, int* __restrict__ off)
{
    __shared__ int sh[1024];
    int carry = 0;
    for (int base = 0; base < N_NODES; base += 1024) {
        int idx = base + threadIdx.x;
        int v = (idx < N_NODES) ? cnt[idx] : 0;
        sh[threadIdx.x] = v;
        __syncthreads();
#pragma unroll
        for (int ofs = 1; ofs < 1024; ofs <<= 1) {
            int t = (threadIdx.x >= ofs) ? sh[threadIdx.x - ofs] : 0;
            __syncthreads();
            sh[threadIdx.x] += t;
            __syncthreads();
        }
        if (idx < N_NODES) off[idx + 1] = carry + sh[threadIdx.x];
        carry += sh[1023];
        __syncthreads();
    }
    if (threadIdx.x == 0) off[0] = 0;
    __syncthreads();
}

__global__ void k_scan()
{
    scan_one(g_cnt_up, g_off_up);
    scan_one(g_cnt_dn, g_off_dn);
}

// ---------------- 4. init fill cursors ----------------
__global__ void k_initcur()
{
    int i = blockIdx.x * blockDim.x + threadIdx.x;
    if (i < N_NODES) { g_cur_up[i] = g_off_up[i]; g_cur_dn[i] = g_off_dn[i]; }
}

// ---------------- 5. CSR fill ----------------
__global__ void k_fill()
{
    int e = blockIdx.x * blockDim.x + threadIdx.x;
    if (e >= N_EDGES) return;
    int r = g_row[e], c = g_col[e];
    int p = atomicAdd(&g_cur_up[c], 1);
    g_csr_up[p] = make_int2(r, e);
    int q = atomicAdd(&g_cur_dn[r], 1);
    g_csr_dn[q] = make_int2(c, e);
}

// ---------------- 6. edge-weight means ----------------
__global__ void k_mean(const float* __restrict__ u1, const float* __restrict__ u2,
                       const float* __restrict__ u3, const float* __restrict__ d1,
                       const float* __restrict__ d2, const float* __restrict__ d3,
                       float* __restrict__ out)
{
    int e = blockIdx.x * blockDim.x + threadIdx.x;
    if (e >= N_EDGES) return;
    out[OUT_MU + e] = (u1[e] + u2[e] + u3[e]) / 3.0f;
    out[OUT_MD + e] = (d1[e] + d2[e] + d3[e]) / 3.0f;
}

// ---------------- 7. fused 3-matrix GEMM per layer ----------------
// 256 threads = 8 nodes x 32 cols per iteration, 8 iterations = 64 nodes/block.
// W tile (96 x DIN) loaded to shared ONCE per block, padded rows (DP) for
// conflict-free float4 loads. Writes tmp_up / tmp_down / bias (no cat buffer).
template <int DIN, int DP>
__global__ void k_gemm(const float* __restrict__ xin, int hsel,
                       const float* __restrict__ wu, const float* __restrict__ wd,
                       const float* __restrict__ wb)
{
    __shared__ float Wsh[96 * DP];
    __shared__ float hsh[8 * DIN];
    const float* h = hsel ? (const float*)g_h : xin;

    int tid = threadIdx.x;
    for (int idx = tid; idx < 96 * DIN; idx += 256) {
        int m = idx / DIN, k = idx % DIN;
        const float* W = (m < 32) ? wu : (m < 64 ? wd : wb);
        Wsh[m * DP + k] = W[(m & 31) * DIN + k];
    }
    __syncthreads();

    int i = tid >> 5;
    int j = tid & 31;
    int n0 = blockIdx.x * 64;
    const float4* A = (const float4*)&Wsh[j * DP];
    const float4* B = (const float4*)&Wsh[(j + 32) * DP];
    const float4* C = (const float4*)&Wsh[(j + 64) * DP];

    for (int it = 0; it < 8; it++) {
        int nb = n0 + it * 8;
        for (int idx = tid; idx < 8 * DIN; idx += 256) {
            int node = nb + idx / DIN;
            hsh[idx] = (node < N_NODES) ? h[node * DIN + idx % DIN] : 0.f;
        }
        __syncthreads();

        float au = 0.f, ad = 0.f, ab = 0.f;
        const float4* H = (const float4*)&hsh[i * DIN];
#pragma unroll
        for (int k4 = 0; k4 < DIN / 4; k4++) {
            float4 hv = H[k4];
            float4 a = A[k4], b = B[k4], c = C[k4];
            au = fmaf(hv.x, a.x, fmaf(hv.y, a.y, fmaf(hv.z, a.z, fmaf(hv.w, a.w, au))));
            ad = fmaf(hv.x, b.x, fmaf(hv.y, b.y, fmaf(hv.z, b.z, fmaf(hv.w, b.w, ad))));
            ab = fmaf(hv.x, c.x, fmaf(hv.y, c.y, fmaf(hv.z, c.z, fmaf(hv.w, c.w, ab))));
        }
        int n = nb + i;
        if (n < N_NODES) {
            g_tmp_up[n * 32 + j]   = au;
            g_tmp_down[n * 32 + j] = ad;
            g_bias[n * 32 + j]     = ab;
        }
        __syncthreads();
    }
}

// ---------------- 8. fused propagate(up) + propagate(down) + norm + leaky ----------------
// One warp per node. Lane j owns feature column j. CSR entries batch-loaded
// coalesced (32 at a time), edge weights gathered in parallel across lanes,
// then shfl-broadcast; tmp[src] rows are coalesced 128B loads. deg_inv comes
// from the segment length. No atomics anywhere.
__device__ __forceinline__ float seg_sum(const int* __restrict__ off,
                                         const int2* __restrict__ csr,
                                         const float* __restrict__ ew,
                                         const float* __restrict__ tmp,
                                         int n, int lane)
{
    int s0 = off[n], s1 = off[n + 1];
    float acc = 0.f;
    for (int base = s0; base < s1; base += 32) {
        int idx = base + lane;
        int2 ent = make_int2(0, 0);
        float wv = 0.f;
        if (idx < s1) {
            ent = csr[idx];
            wv = ew[ent.y];
        }
        int cnt = min(32, s1 - base);
#pragma unroll 4
        for (int t = 0; t < cnt; t++) {
            int   s = __shfl_sync(0xFFFFFFFFu, ent.x, t);
            float w = __shfl_sync(0xFFFFFFFFu, wv, t);
            acc = fmaf(w, tmp[s * 32 + lane], acc);
        }
    }
    int deg = s1 - s0;
    return deg > 0 ? acc * (1.0f / (float)deg) : 0.f;
}

__global__ void k_prop_norm(const float* __restrict__ ewu,
                            const float* __restrict__ ewd,
                            float* __restrict__ out, int toOut)
{
    int gt = blockIdx.x * blockDim.x + threadIdx.x;
    int n = gt >> 5;
    int lane = gt & 31;
    if (n >= N_NODES) return;

    float up = seg_sum(g_off_up, g_csr_up, ewu, g_tmp_up,   n, lane);
    float dn = seg_sum(g_off_dn, g_csr_dn, ewd, g_tmp_down, n, lane);
    float b  = g_bias[n * 32 + lane];

    float ss = up * up + dn * dn + b * b;
#pragma unroll
    for (int o = 16; o; o >>= 1) ss += __shfl_xor_sync(0xFFFFFFFFu, ss, o);
    float inv = 1.0f / fmaxf(sqrtf(ss), 1e-12f);

    float va = up * inv; va = va >= 0.f ? va : 0.1f * va;
    float vb = dn * inv; vb = vb >= 0.f ? vb : 0.1f * vb;
    float vc = b  * inv; vc = vc >= 0.f ? vc : 0.1f * vc;

    float* dstp = toOut ? out : (float*)g_h;
    dstp[n * 96 + lane]      = va;
    dstp[n * 96 + 32 + lane] = vb;
    dstp[n * 96 + 64 + lane] = vc;
}

// ---------------- host launch ----------------
extern "C" void kernel_launch(void* const* d_in, const int* in_sizes, int n_in,
                              void* d_out, int out_size)
{
    const float* x   = (const float*)d_in[0];
    const int*   ei  = (const int*)d_in[1];
    const float* w1u = (const float*)d_in[2];
    const float* w1d = (const float*)d_in[3];
    const float* w1b = (const float*)d_in[4];
    const float* e1u = (const float*)d_in[5];
    const float* e1d = (const float*)d_in[6];
    const float* w2u = (const float*)d_in[7];
    const float* w2d = (const float*)d_in[8];
    const float* w2b = (const float*)d_in[9];
    const float* e2u = (const float*)d_in[10];
    const float* e2d = (const float*)d_in[11];
    const float* w3u = (const float*)d_in[12];
    const float* w3d = (const float*)d_in[13];
    const float* w3b = (const float*)d_in[14];
    const float* e3u = (const float*)d_in[15];
    const float* e3d = (const float*)d_in[16];
    float* out = (float*)d_out;

    const int NB_N    = (N_NODES + 255) / 256;             // 196
    const int NB_E    = N_EDGES / 256;                     // 6250
    const int NB_GEMM = (N_NODES + 63) / 64;               // 782
    const int NB_PROP = (N_NODES * 32 + 255) / 256;        // 6250

    // ---- prep + CSR build (graph shared by all 3 layers, both directions) ----
    k_detect<<<1, 256>>>(ei);
    k_zero<<<NB_N, 256>>>();
    k_prep<<<NB_E, 256>>>(ei);
    k_scan<<<1, 1024>>>();
    k_initcur<<<NB_N, 256>>>();
    k_fill<<<NB_E, 256>>>();
    k_mean<<<NB_E, 256>>>(e1u, e2u, e3u, e1d, e2d, e3d, out);

    // ---- layer 1 ----
    k_gemm<8, 12><<<NB_GEMM, 256>>>(x, 0, w1u, w1d, w1b);
    k_prop_norm<<<NB_PROP, 256>>>(e1u, e1d, nullptr, 0);

    // ---- layer 2 ----
    k_gemm<96, 100><<<NB_GEMM, 256>>>(nullptr, 1, w2u, w2d, w2b);
    k_prop_norm<<<NB_PROP, 256>>>(e2u, e2d, nullptr, 0);

    // ---- layer 3 ----
    k_gemm<96, 100><<<NB_GEMM, 256>>>(nullptr, 1, w3u, w3d, w3b);
    k_prop_norm<<<NB_PROP, 256>>>(e3u, e3d, out, 1);
}

// round 13
// speedup vs baseline: 3.1555x; 1.4419x over previous
#include <cuda_runtime.h>
#include <cuda_bf16.h>

#define N_NODES 50000
#define N_EDGES 1600000
#define OUT_H   (N_NODES * 96)
#define OUT_MU  OUT_H
#define OUT_MD  (OUT_H + N_EDGES)
#define NBLK_SCAN 49   // ceil(50000/1024)

// ---------------- scratch (device globals; no allocation allowed) ----------------
__device__ int   g_is64;
__device__ __align__(16) int   g_row[N_EDGES];
__device__ __align__(16) int   g_col[N_EDGES];
__device__ int   g_cnt_up[N_NODES];
__device__ int   g_cnt_dn[N_NODES];
__device__ int   g_off_up[N_NODES + 1];
__device__ int   g_off_dn[N_NODES + 1];
__device__ int   g_cur_up[N_NODES];
__device__ int   g_cur_dn[N_NODES];
__device__ int   g_part[2][64];
__device__ __align__(16) int2  g_csr_up[N_EDGES];   // (src=row, eid), bucketed by col
__device__ __align__(16) int2  g_csr_dn[N_EDGES];   // (src=col, eid), bucketed by row
__device__ __align__(16) float g_tmp_up[N_NODES * 32];
__device__ __align__(16) float g_tmp_down[N_NODES * 32];
__device__ __align__(16) float g_bias[N_NODES * 32];
__device__ __align__(16) float g_h[N_NODES * 96];

// ---------------- 0. zero counters + detect int64 vs int32 (block 0) ----------------
__global__ void k_zero_detect(const int* __restrict__ ei)
{
    int i = blockIdx.x * blockDim.x + threadIdx.x;
    if (i < N_NODES) { g_cnt_up[i] = 0; g_cnt_dn[i] = 0; }
    if (blockIdx.x == 0) {
        __shared__ int sh[256];
        int acc = 0;
        for (int k = threadIdx.x; k < 2048; k += 256)
            acc |= ei[2 * k + 1];
        sh[threadIdx.x] = acc;
        __syncthreads();
        for (int s = 128; s; s >>= 1) {
            if (threadIdx.x < s) sh[threadIdx.x] |= sh[threadIdx.x + s];
            __syncthreads();
        }
        if (threadIdx.x == 0) g_is64 = (sh[0] == 0) ? 1 : 0;
    }
}

// ---------------- 1. convert edge index + count degrees ----------------
__global__ void k_prep(const int* __restrict__ ei)
{
    int e = blockIdx.x * blockDim.x + threadIdx.x;
    if (e >= N_EDGES) return;
    int r, c;
    if (g_is64) {
        r = ei[2 * e];
        c = ei[2 * (N_EDGES + e)];
    } else {
        r = ei[e];
        c = ei[N_EDGES + e];
    }
    g_row[e] = r;
    g_col[e] = c;
    atomicAdd(&g_cnt_up[c], 1);
    atomicAdd(&g_cnt_dn[r], 1);
}

// ---------------- 2a. per-block inclusive scan ----------------
__global__ void k_blockscan()   // grid (NBLK_SCAN, 2), block 1024
{
    __shared__ int sh[1024];
    const int* cnt = blockIdx.y ? g_cnt_dn : g_cnt_up;
    int* off = blockIdx.y ? g_off_dn : g_off_up;
    int idx = blockIdx.x * 1024 + threadIdx.x;
    sh[threadIdx.x] = (idx < N_NODES) ? cnt[idx] : 0;
    __syncthreads();
#pragma unroll
    for (int ofs = 1; ofs < 1024; ofs <<= 1) {
        int t = (threadIdx.x >= ofs) ? sh[threadIdx.x - ofs] : 0;
        __syncthreads();
        sh[threadIdx.x] += t;
        __syncthreads();
    }
    if (idx < N_NODES) off[idx + 1] = sh[threadIdx.x];
    if (threadIdx.x == 1023) g_part[blockIdx.y][blockIdx.x] = sh[1023];
}

// ---------------- 2b. scan the block partials (tiny) ----------------
__global__ void k_scanpart()
{
    if (threadIdx.x < 2) {
        int* p = g_part[threadIdx.x];
        int acc = 0;
        for (int i = 0; i < NBLK_SCAN; i++) { int t = p[i]; p[i] = acc; acc += t; }
    }
}

// ---------------- 2c. add carries + init fill cursors ----------------
__global__ void k_addcarry()    // grid (NBLK_SCAN, 2), block 1024
{
    int idx = blockIdx.x * 1024 + threadIdx.x;
    if (idx >= N_NODES) return;
    int* off = blockIdx.y ? g_off_dn : g_off_up;
    int* cur = blockIdx.y ? g_cur_dn : g_cur_up;
    int v = off[idx + 1] + g_part[blockIdx.y][blockIdx.x];
    off[idx + 1] = v;
    if (idx + 1 < N_NODES) cur[idx + 1] = v;
    if (idx == 0) { off[0] = 0; cur[0] = 0; }
}

// ---------------- 3. CSR fill + edge-weight means (fused) ----------------
__global__ void k_fillmean(const float* __restrict__ u1, const float* __restrict__ u2,
                           const float* __restrict__ u3, const float* __restrict__ d1,
                           const float* __restrict__ d2, const float* __restrict__ d3,
                           float* __restrict__ out)
{
    int e = blockIdx.x * blockDim.x + threadIdx.x;
    if (e >= N_EDGES) return;
    int r = g_row[e], c = g_col[e];
    int p = atomicAdd(&g_cur_up[c], 1);
    g_csr_up[p] = make_int2(r, e);
    int q = atomicAdd(&g_cur_dn[r], 1);
    g_csr_dn[q] = make_int2(c, e);
    out[OUT_MU + e] = (u1[e] + u2[e] + u3[e]) / 3.0f;
    out[OUT_MD + e] = (d1[e] + d2[e] + d3[e]) / 3.0f;
}

// ---------------- 4. fused 3-matrix GEMM, 2 nodes per thread ----------------
// 256 threads. Warp w handles nodes {2w, 2w+1} per iter (16 nodes/iter),
// 8 iters = 128 nodes/block. W tile staged to shared once per block with
// padded rows (DP) for conflict-free float4 lane access.
template <int DIN, int DP>
__global__ void k_gemm(const float* __restrict__ xin, int hsel,
                       const float* __restrict__ wu, const float* __restrict__ wd,
                       const float* __restrict__ wb)
{
    __shared__ float Wsh[96 * DP];
    __shared__ float hsh[16 * DIN];
    const float* h = hsel ? (const float*)g_h : xin;

    int tid = threadIdx.x;
    for (int idx = tid; idx < 96 * DIN; idx += 256) {
        int m = idx / DIN, k = idx % DIN;
        const float* W = (m < 32) ? wu : (m < 64 ? wd : wb);
        Wsh[m * DP + k] = W[(m & 31) * DIN + k];
    }
    __syncthreads();

    int i = tid >> 5;       // warp id: nodes 2i, 2i+1 within the 16-node tile
    int j = tid & 31;       // output column
    int n0 = blockIdx.x * 128;
    const float4* A = (const float4*)&Wsh[j * DP];
    const float4* B = (const float4*)&Wsh[(j + 32) * DP];
    const float4* C = (const float4*)&Wsh[(j + 64) * DP];

    for (int it = 0; it < 8; it++) {
        int nb = n0 + it * 16;
        for (int idx = tid; idx < 16 * DIN; idx += 256) {
            int node = nb + idx / DIN;
            hsh[idx] = (node < N_NODES) ? h[node * DIN + idx % DIN] : 0.f;
        }
        __syncthreads();

        float au0 = 0.f, ad0 = 0.f, ab0 = 0.f;
        float au1 = 0.f, ad1 = 0.f, ab1 = 0.f;
        const float4* H0 = (const float4*)&hsh[(2 * i) * DIN];
        const float4* H1 = (const float4*)&hsh[(2 * i + 1) * DIN];
#pragma unroll
        for (int k4 = 0; k4 < DIN / 4; k4++) {
            float4 a = A[k4], b = B[k4], c = C[k4];
            float4 h0 = H0[k4], h1 = H1[k4];
            au0 = fmaf(h0.x, a.x, fmaf(h0.y, a.y, fmaf(h0.z, a.z, fmaf(h0.w, a.w, au0))));
            ad0 = fmaf(h0.x, b.x, fmaf(h0.y, b.y, fmaf(h0.z, b.z, fmaf(h0.w, b.w, ad0))));
            ab0 = fmaf(h0.x, c.x, fmaf(h0.y, c.y, fmaf(h0.z, c.z, fmaf(h0.w, c.w, ab0))));
            au1 = fmaf(h1.x, a.x, fmaf(h1.y, a.y, fmaf(h1.z, a.z, fmaf(h1.w, a.w, au1))));
            ad1 = fmaf(h1.x, b.x, fmaf(h1.y, b.y, fmaf(h1.z, b.z, fmaf(h1.w, b.w, ad1))));
            ab1 = fmaf(h1.x, c.x, fmaf(h1.y, c.y, fmaf(h1.z, c.z, fmaf(h1.w, c.w, ab1))));
        }
        int na = nb + 2 * i, nbb = na + 1;
        if (na < N_NODES) {
            g_tmp_up[na * 32 + j]   = au0;
            g_tmp_down[na * 32 + j] = ad0;
            g_bias[na * 32 + j]     = ab0;
        }
        if (nbb < N_NODES) {
            g_tmp_up[nbb * 32 + j]   = au1;
            g_tmp_down[nbb * 32 + j] = ad1;
            g_bias[nbb * 32 + j]     = ab1;
        }
        __syncthreads();
    }
}

// ---------------- 5. fused propagate(up+down) + norm + leaky ----------------
// One warp per node, lane = feature column. (src, w) batches staged through
// shared memory (broadcast LDS instead of 2x SHFL per edge); dual accumulators
// break the dependent FFMA chain.
__device__ __forceinline__ float seg_sum(const int* __restrict__ off,
                                         const int2* __restrict__ csr,
                                         const float* __restrict__ ew,
                                         const float* __restrict__ tmp,
                                         int n, int lane, int2* __restrict__ stg)
{
    int s0 = off[n], s1 = off[n + 1];
    float acc0 = 0.f, acc1 = 0.f;
    for (int base = s0; base < s1; base += 32) {
        int idx = base + lane;
        if (idx < s1) {
            int2 ent = csr[idx];
            stg[lane] = make_int2(ent.x, __float_as_int(ew[ent.y]));
        }
        __syncwarp();
        int cnt = min(32, s1 - base);
        int t = 0;
        for (; t + 2 <= cnt; t += 2) {
            int2 e0 = stg[t], e1 = stg[t + 1];
            acc0 = fmaf(__int_as_float(e0.y), tmp[e0.x * 32 + lane], acc0);
            acc1 = fmaf(__int_as_float(e1.y), tmp[e1.x * 32 + lane], acc1);
        }
        if (t < cnt) {
            int2 e0 = stg[t];
            acc0 = fmaf(__int_as_float(e0.y), tmp[e0.x * 32 + lane], acc0);
        }
        __syncwarp();
    }
    int deg = s1 - s0;
    return deg > 0 ? (acc0 + acc1) * (1.0f / (float)deg) : 0.f;
}

__global__ void k_prop_norm(const float* __restrict__ ewu,
                            const float* __restrict__ ewd,
                            float* __restrict__ out, int toOut)
{
    __shared__ int2 stage[8][32];
    int gt = blockIdx.x * blockDim.x + threadIdx.x;
    int n = gt >> 5;
    int lane = gt & 31;
    int wid = (threadIdx.x >> 5);
    if (n >= N_NODES) return;

    float up = seg_sum(g_off_up, g_csr_up, ewu, g_tmp_up,   n, lane, stage[wid]);
    float dn = seg_sum(g_off_dn, g_csr_dn, ewd, g_tmp_down, n, lane, stage[wid]);
    float b  = g_bias[n * 32 + lane];

    float ss = up * up + dn * dn + b * b;
#pragma unroll
    for (int o = 16; o; o >>= 1) ss += __shfl_xor_sync(0xFFFFFFFFu, ss, o);
    float inv = 1.0f / fmaxf(sqrtf(ss), 1e-12f);

    float va = up * inv; va = va >= 0.f ? va : 0.1f * va;
    float vb = dn * inv; vb = vb >= 0.f ? vb : 0.1f * vb;
    float vc = b  * inv; vc = vc >= 0.f ? vc : 0.1f * vc;

    float* dstp = toOut ? out : (float*)g_h;
    dstp[n * 96 + lane]      = va;
    dstp[n * 96 + 32 + lane] = vb;
    dstp[n * 96 + 64 + lane] = vc;
}

// ---------------- host launch ----------------
extern "C" void kernel_launch(void* const* d_in, const int* in_sizes, int n_in,
                              void* d_out, int out_size)
{
    const float* x   = (const float*)d_in[0];
    const int*   ei  = (const int*)d_in[1];
    const float* w1u = (const float*)d_in[2];
    const float* w1d = (const float*)d_in[3];
    const float* w1b = (const float*)d_in[4];
    const float* e1u = (const float*)d_in[5];
    const float* e1d = (const float*)d_in[6];
    const float* w2u = (const float*)d_in[7];
    const float* w2d = (const float*)d_in[8];
    const float* w2b = (const float*)d_in[9];
    const float* e2u = (const float*)d_in[10];
    const float* e2d = (const float*)d_in[11];
    const float* w3u = (const float*)d_in[12];
    const float* w3d = (const float*)d_in[13];
    const float* w3b = (const float*)d_in[14];
    const float* e3u = (const float*)d_in[15];
    const float* e3d = (const float*)d_in[16];
    float* out = (float*)d_out;

    const int NB_N    = (N_NODES + 255) / 256;             // 196
    const int NB_E    = N_EDGES / 256;                     // 6250
    const int NB_GEMM = (N_NODES + 127) / 128;             // 391
    const int NB_PROP = (N_NODES * 32 + 255) / 256;        // 6250
    dim3 scan_grid(NBLK_SCAN, 2);

    // ---- prep + CSR build ----
    k_zero_detect<<<NB_N, 256>>>(ei);
    k_prep<<<NB_E, 256>>>(ei);
    k_blockscan<<<scan_grid, 1024>>>();
    k_scanpart<<<1, 32>>>();
    k_addcarry<<<scan_grid, 1024>>>();
    k_fillmean<<<NB_E, 256>>>(e1u, e2u, e3u, e1d, e2d, e3d, out);

    // ---- layer 1 ----
    k_gemm<8, 12><<<NB_GEMM, 256>>>(x, 0, w1u, w1d, w1b);
    k_prop_norm<<<NB_PROP, 256>>>(e1u, e1d, nullptr, 0);

    // ---- layer 2 ----
    k_gemm<96, 100><<<NB_GEMM, 256>>>(nullptr, 1, w2u, w2d, w2b);
    k_prop_norm<<<NB_PROP, 256>>>(e2u, e2d, nullptr, 0);

    // ---- layer 3 ----
    k_gemm<96, 100><<<NB_GEMM, 256>>>(nullptr, 1, w3u, w3d, w3b);
    k_prop_norm<<<NB_PROP, 256>>>(e3u, e3d, out, 1);
}